// round 9
// baseline (speedup 1.0000x reference)
#include <cuda_runtime.h>
#include <cuda_bf16.h>
#include <cstdint>

// MinimalThinkingRefiner: out = x + alpha*(x*scale + shift) where mask[row]==2, else x.
// One CTA per row; full 256-bit load AND store streams (ld/st.global.v8.b32) to
// minimize LSU wavefronts per byte and maximize DRAM burst size.

__device__ __forceinline__ void ldg_v8(const float4* p, float4& a, float4& b) {
    asm("ld.global.v8.b32 {%0,%1,%2,%3,%4,%5,%6,%7}, [%8];"
        : "=f"(a.x), "=f"(a.y), "=f"(a.z), "=f"(a.w),
          "=f"(b.x), "=f"(b.y), "=f"(b.z), "=f"(b.w)
        : "l"(p));
}

__device__ __forceinline__ void stg_v8(float4* p, const float4& a, const float4& b) {
    asm volatile("st.global.v8.b32 [%0], {%1,%2,%3,%4,%5,%6,%7,%8};"
        :: "l"(p),
           "f"(a.x), "f"(a.y), "f"(a.z), "f"(a.w),
           "f"(b.x), "f"(b.y), "f"(b.z), "f"(b.w)
        : "memory");
}

__global__ void __launch_bounds__(256, 8)
refiner_kernel(const float4* __restrict__ x,
               const int*    __restrict__ mask,
               const float4* __restrict__ scale,
               const float4* __restrict__ shift,
               const float*  __restrict__ alpha_p,
               float4* __restrict__ out,
               int hv8 /* H/8 : 32-byte chunks per row */)
{
    const int row = blockIdx.x;
    const bool thinking = (mask[row] == 2);
    const size_t base = (size_t)row * hv8 * 2;
    const float4* __restrict__ xr = x + base;
    float4* __restrict__ orow = out + base;

    if (!thinking) {
        // pure streaming copy, 32 B per instruction
        #pragma unroll 2
        for (int i = threadIdx.x; i < hv8; i += blockDim.x) {
            float4 a, b;
            ldg_v8(&xr[2 * i], a, b);
            stg_v8(&orow[2 * i], a, b);
        }
    } else {
        const float al = __ldg(alpha_p);
        #pragma unroll 2
        for (int i = threadIdx.x; i < hv8; i += blockDim.x) {
            float4 a, b, s0, s1, t0, t1;
            ldg_v8(&xr[2 * i], a, b);
            ldg_v8(&scale[2 * i], s0, s1);
            ldg_v8(&shift[2 * i], t0, t1);
            a.x = fmaf(al, fmaf(a.x, s0.x, t0.x), a.x);
            a.y = fmaf(al, fmaf(a.y, s0.y, t0.y), a.y);
            a.z = fmaf(al, fmaf(a.z, s0.z, t0.z), a.z);
            a.w = fmaf(al, fmaf(a.w, s0.w, t0.w), a.w);
            b.x = fmaf(al, fmaf(b.x, s1.x, t1.x), b.x);
            b.y = fmaf(al, fmaf(b.y, s1.y, t1.y), b.y);
            b.z = fmaf(al, fmaf(b.z, s1.z, t1.z), b.z);
            b.w = fmaf(al, fmaf(b.w, s1.w, t1.w), b.w);
            stg_v8(&orow[2 * i], a, b);
        }
    }
}

extern "C" void kernel_launch(void* const* d_in, const int* in_sizes, int n_in,
                              void* d_out, int out_size)
{
    const float* x     = (const float*)d_in[0];   // [B,S,H]
    const int*   mask  = (const int*)d_in[1];     // [B,S]
    const float* scale = (const float*)d_in[2];   // [H]
    const float* shift = (const float*)d_in[3];   // [H]
    const float* alpha = (const float*)d_in[4];   // scalar

    const int rows = in_sizes[1];                 // B*S (16384)
    const int H    = in_sizes[0] / rows;          // 4096
    const int hv8  = H / 8;                       // 32-byte chunks per row (512)

    refiner_kernel<<<rows, 256>>>(
        (const float4*)x, mask, (const float4*)scale, (const float4*)shift,
        alpha, (float4*)d_out, hv8);
}

// round 10
// speedup vs baseline: 1.0308x; 1.0308x over previous
#include <cuda_runtime.h>
#include <cuda_bf16.h>
#include <cstdint>

// MinimalThinkingRefiner: out = x + alpha*(x*scale + shift) where mask[row]==2, else x.
// One CTA (512 threads) per row; H/8 == 512 so each thread moves exactly one 32-byte
// chunk: straight-line body, no loop, minimal per-CTA lifetime.

__device__ __forceinline__ void ldg_v8(const float4* p, float4& a, float4& b) {
    asm("ld.global.v8.b32 {%0,%1,%2,%3,%4,%5,%6,%7}, [%8];"
        : "=f"(a.x), "=f"(a.y), "=f"(a.z), "=f"(a.w),
          "=f"(b.x), "=f"(b.y), "=f"(b.z), "=f"(b.w)
        : "l"(p));
}

__device__ __forceinline__ void stg_v8(float4* p, const float4& a, const float4& b) {
    asm volatile("st.global.v8.b32 [%0], {%1,%2,%3,%4,%5,%6,%7,%8};"
        :: "l"(p),
           "f"(a.x), "f"(a.y), "f"(a.z), "f"(a.w),
           "f"(b.x), "f"(b.y), "f"(b.z), "f"(b.w)
        : "memory");
}

__device__ __forceinline__ void refine_chunk(float4& a, float4& b,
                                             const float4* scale, const float4* shift,
                                             int c, float al)
{
    float4 s0, s1, t0, t1;
    ldg_v8(&scale[2 * c], s0, s1);
    ldg_v8(&shift[2 * c], t0, t1);
    a.x = fmaf(al, fmaf(a.x, s0.x, t0.x), a.x);
    a.y = fmaf(al, fmaf(a.y, s0.y, t0.y), a.y);
    a.z = fmaf(al, fmaf(a.z, s0.z, t0.z), a.z);
    a.w = fmaf(al, fmaf(a.w, s0.w, t0.w), a.w);
    b.x = fmaf(al, fmaf(b.x, s1.x, t1.x), b.x);
    b.y = fmaf(al, fmaf(b.y, s1.y, t1.y), b.y);
    b.z = fmaf(al, fmaf(b.z, s1.z, t1.z), b.z);
    b.w = fmaf(al, fmaf(b.w, s1.w, t1.w), b.w);
}

// Specialized: blockDim.x == hv8 (one chunk per thread, no loop).
__global__ void __launch_bounds__(512, 4)
refiner_flat(const float4* __restrict__ x,
             const int*    __restrict__ mask,
             const float4* __restrict__ scale,
             const float4* __restrict__ shift,
             const float*  __restrict__ alpha_p,
             float4* __restrict__ out)
{
    const int row = blockIdx.x;
    const int c   = threadIdx.x;                       // chunk index in row
    const size_t base = ((size_t)row * blockDim.x + c) * 2;

    float4 a, b;
    ldg_v8(&x[base], a, b);
    if (mask[row] == 2) {
        refine_chunk(a, b, scale, shift, c, __ldg(alpha_p));
    }
    stg_v8(&out[base], a, b);
}

// General fallback: loop over chunks.
__global__ void __launch_bounds__(256, 8)
refiner_loop(const float4* __restrict__ x,
             const int*    __restrict__ mask,
             const float4* __restrict__ scale,
             const float4* __restrict__ shift,
             const float*  __restrict__ alpha_p,
             float4* __restrict__ out,
             int hv8)
{
    const int row = blockIdx.x;
    const bool thinking = (mask[row] == 2);
    const size_t base = (size_t)row * hv8 * 2;
    const float4* __restrict__ xr = x + base;
    float4* __restrict__ orow = out + base;
    const float al = thinking ? __ldg(alpha_p) : 0.0f;

    #pragma unroll 2
    for (int i = threadIdx.x; i < hv8; i += blockDim.x) {
        float4 a, b;
        ldg_v8(&xr[2 * i], a, b);
        if (thinking) refine_chunk(a, b, scale, shift, i, al);
        stg_v8(&orow[2 * i], a, b);
    }
}

extern "C" void kernel_launch(void* const* d_in, const int* in_sizes, int n_in,
                              void* d_out, int out_size)
{
    const float* x     = (const float*)d_in[0];   // [B,S,H]
    const int*   mask  = (const int*)d_in[1];     // [B,S]
    const float* scale = (const float*)d_in[2];   // [H]
    const float* shift = (const float*)d_in[3];   // [H]
    const float* alpha = (const float*)d_in[4];   // scalar

    const int rows = in_sizes[1];                 // B*S (16384)
    const int H    = in_sizes[0] / rows;          // 4096
    const int hv8  = H / 8;                       // 32-byte chunks per row (512)

    if (hv8 == 512) {
        refiner_flat<<<rows, 512>>>(
            (const float4*)x, mask, (const float4*)scale, (const float4*)shift,
            alpha, (float4*)d_out);
    } else {
        refiner_loop<<<rows, 256>>>(
            (const float4*)x, mask, (const float4*)scale, (const float4*)shift,
            alpha, (float4*)d_out, hv8);
    }
}

// round 11
// speedup vs baseline: 1.0312x; 1.0004x over previous
#include <cuda_runtime.h>
#include <cuda_bf16.h>
#include <cstdint>

// MinimalThinkingRefiner: out = x + alpha*(x*scale + shift) where mask[row]==2, else x.
// One CTA (256 threads) per HALF-row; each thread moves exactly one 32-byte chunk.
// Straight-line body, minimal CTA lifetime, fine-grained tail.

__device__ __forceinline__ void ldg_v8(const float4* p, float4& a, float4& b) {
    asm("ld.global.v8.b32 {%0,%1,%2,%3,%4,%5,%6,%7}, [%8];"
        : "=f"(a.x), "=f"(a.y), "=f"(a.z), "=f"(a.w),
          "=f"(b.x), "=f"(b.y), "=f"(b.z), "=f"(b.w)
        : "l"(p));
}

__device__ __forceinline__ void stg_v8(float4* p, const float4& a, const float4& b) {
    asm volatile("st.global.v8.b32 [%0], {%1,%2,%3,%4,%5,%6,%7,%8};"
        :: "l"(p),
           "f"(a.x), "f"(a.y), "f"(a.z), "f"(a.w),
           "f"(b.x), "f"(b.y), "f"(b.z), "f"(b.w)
        : "memory");
}

__device__ __forceinline__ void refine_chunk(float4& a, float4& b,
                                             const float4* scale, const float4* shift,
                                             int c, float al)
{
    float4 s0, s1, t0, t1;
    ldg_v8(&scale[2 * c], s0, s1);
    ldg_v8(&shift[2 * c], t0, t1);
    a.x = fmaf(al, fmaf(a.x, s0.x, t0.x), a.x);
    a.y = fmaf(al, fmaf(a.y, s0.y, t0.y), a.y);
    a.z = fmaf(al, fmaf(a.z, s0.z, t0.z), a.z);
    a.w = fmaf(al, fmaf(a.w, s0.w, t0.w), a.w);
    b.x = fmaf(al, fmaf(b.x, s1.x, t1.x), b.x);
    b.y = fmaf(al, fmaf(b.y, s1.y, t1.y), b.y);
    b.z = fmaf(al, fmaf(b.z, s1.z, t1.z), b.z);
    b.w = fmaf(al, fmaf(b.w, s1.w, t1.w), b.w);
}

// Specialized: hv8 == 512. One CTA per half-row, 256 threads, one chunk/thread.
__global__ void __launch_bounds__(256, 8)
refiner_half(const float4* __restrict__ x,
             const int*    __restrict__ mask,
             const float4* __restrict__ scale,
             const float4* __restrict__ shift,
             const float*  __restrict__ alpha_p,
             float4* __restrict__ out)
{
    const int row  = blockIdx.x >> 1;
    const int c    = ((blockIdx.x & 1) << 8) + threadIdx.x;   // chunk index in row
    const size_t base = ((size_t)row << 10) + ((size_t)c << 1); // row*512*2 + c*2

    float4 a, b;
    ldg_v8(&x[base], a, b);
    if (mask[row] == 2) {
        refine_chunk(a, b, scale, shift, c, __ldg(alpha_p));
    }
    stg_v8(&out[base], a, b);
}

// General fallback: loop over chunks.
__global__ void __launch_bounds__(256, 8)
refiner_loop(const float4* __restrict__ x,
             const int*    __restrict__ mask,
             const float4* __restrict__ scale,
             const float4* __restrict__ shift,
             const float*  __restrict__ alpha_p,
             float4* __restrict__ out,
             int hv8)
{
    const int row = blockIdx.x;
    const bool thinking = (mask[row] == 2);
    const size_t base = (size_t)row * hv8 * 2;
    const float4* __restrict__ xr = x + base;
    float4* __restrict__ orow = out + base;
    const float al = thinking ? __ldg(alpha_p) : 0.0f;

    #pragma unroll 2
    for (int i = threadIdx.x; i < hv8; i += blockDim.x) {
        float4 a, b;
        ldg_v8(&xr[2 * i], a, b);
        if (thinking) refine_chunk(a, b, scale, shift, i, al);
        stg_v8(&orow[2 * i], a, b);
    }
}

extern "C" void kernel_launch(void* const* d_in, const int* in_sizes, int n_in,
                              void* d_out, int out_size)
{
    const float* x     = (const float*)d_in[0];   // [B,S,H]
    const int*   mask  = (const int*)d_in[1];     // [B,S]
    const float* scale = (const float*)d_in[2];   // [H]
    const float* shift = (const float*)d_in[3];   // [H]
    const float* alpha = (const float*)d_in[4];   // scalar

    const int rows = in_sizes[1];                 // B*S (16384)
    const int H    = in_sizes[0] / rows;          // 4096
    const int hv8  = H / 8;                       // 32-byte chunks per row (512)

    if (hv8 == 512) {
        refiner_half<<<rows * 2, 256>>>(
            (const float4*)x, mask, (const float4*)scale, (const float4*)shift,
            alpha, (float4*)d_out);
    } else {
        refiner_loop<<<rows, 256>>>(
            (const float4*)x, mask, (const float4*)scale, (const float4*)shift,
            alpha, (float4*)d_out, hv8);
    }
}